// round 6
// baseline (speedup 1.0000x reference)
#include <cuda_runtime.h>
#include <math.h>
#include <stdint.h>

#define N_CTX   4096
#define D_MODEL 2048

#define BM 128
#define BN 128
#define BK 16
#define TM 8
#define TN 8
// 256 threads per CTA: 16x16 thread grid, each thread owns an 8x8 microtile.

// Scratch (allocation-free rule: __device__ globals)
__device__ float g_Q[(size_t)N_CTX * D_MODEL];   // 32 MB : E @ qk
__device__ float g_V[(size_t)N_CTX * D_MODEL];   // 32 MB : E @ ov
__device__ float g_S[(size_t)N_CTX * N_CTX];     // 64 MB : scores -> probs

// ---------------------------------------------------------------------------
// Tiled fp32 GEMM.
//   C[M,N] = A[M,K] @ op(B),  op(B) = B[K,N] (BT=false)  or  B[N,K]^T (BT=true)
//   SKIP_UPPER : (square, BM==BN) skip blocks with col-block > row-block
//   KLIMIT     : K effective = min(K, (rowblock+1)*BM)   (causal P @ V)
//   MASK       : write -inf where global_col > global_row (causal scores)
// ---------------------------------------------------------------------------
template<bool BT, bool SKIP_UPPER, bool KLIMIT, bool MASK>
__global__ __launch_bounds__(256, 2)
void gemm_kernel(const float* __restrict__ A, const float* __restrict__ B,
                 float* __restrict__ C, int M, int N, int K,
                 int lda, int ldb, int ldc)
{
    const int bx = blockIdx.x;   // column block
    const int by = blockIdx.y;   // row block

    if (SKIP_UPPER && bx > by) return;

    int Kend = K;
    if (KLIMIT) {
        int lim = (by + 1) * BM;
        Kend = lim < K ? lim : K;
    }

    __shared__ float As[BK][BM];
    __shared__ float Bs[BK][BN];

    const int tid = threadIdx.x;
    const int tx = tid & 15;      // 0..15 -> column group
    const int ty = tid >> 4;      // 0..15 -> row group

    float acc[TM][TN];
#pragma unroll
    for (int i = 0; i < TM; i++)
#pragma unroll
        for (int j = 0; j < TN; j++) acc[i][j] = 0.0f;

    // loader coordinates
    const int lr  = tid >> 2;         // 0..63  (row within 128-row tile, +64 second half)
    const int lc4 = (tid & 3) << 2;   // 0,4,8,12 (k offset, float4)
    const int brk = tid >> 5;         // 0..7   (k row for NN B tile, +8 second half)
    const int bc  = (tid & 31) << 2;  // 0..124 (n offset, float4)

    const int rowA0 = by * BM;
    const int colB0 = bx * BN;

    for (int k0 = 0; k0 < Kend; k0 += BK) {
        // ---- load A tile [BM x BK], store transposed As[k][m]
#pragma unroll
        for (int it = 0; it < 2; it++) {
            int r = lr + it * 64;
            float4 v = *(const float4*)&A[(size_t)(rowA0 + r) * lda + k0 + lc4];
            As[lc4 + 0][r] = v.x;
            As[lc4 + 1][r] = v.y;
            As[lc4 + 2][r] = v.z;
            As[lc4 + 3][r] = v.w;
        }
        // ---- load B tile
        if (BT) {
            // B is [N,K]: tile rows are N, transpose into Bs[k][n]
#pragma unroll
            for (int it = 0; it < 2; it++) {
                int r = lr + it * 64;
                float4 v = *(const float4*)&B[(size_t)(colB0 + r) * ldb + k0 + lc4];
                Bs[lc4 + 0][r] = v.x;
                Bs[lc4 + 1][r] = v.y;
                Bs[lc4 + 2][r] = v.z;
                Bs[lc4 + 3][r] = v.w;
            }
        } else {
            // B is [K,N]: direct copy Bs[k][n]
#pragma unroll
            for (int it = 0; it < 2; it++) {
                int kk = brk + it * 8;
                float4 v = *(const float4*)&B[(size_t)(k0 + kk) * ldb + colB0 + bc];
                *(float4*)&Bs[kk][bc] = v;
            }
        }
        __syncthreads();

#pragma unroll
        for (int kk = 0; kk < BK; kk++) {
            float4 a0 = *(const float4*)&As[kk][ty * TM];
            float4 a1 = *(const float4*)&As[kk][ty * TM + 4];
            float4 b0 = *(const float4*)&Bs[kk][tx * TN];
            float4 b1 = *(const float4*)&Bs[kk][tx * TN + 4];
            float a[TM] = {a0.x, a0.y, a0.z, a0.w, a1.x, a1.y, a1.z, a1.w};
            float b[TN] = {b0.x, b0.y, b0.z, b0.w, b1.x, b1.y, b1.z, b1.w};
#pragma unroll
            for (int i = 0; i < TM; i++)
#pragma unroll
                for (int j = 0; j < TN; j++)
                    acc[i][j] = fmaf(a[i], b[j], acc[i][j]);
        }
        __syncthreads();
    }

    // ---- epilogue
    const int row0 = rowA0 + ty * TM;
    const int col0 = colB0 + tx * TN;
#pragma unroll
    for (int i = 0; i < TM; i++) {
        int grow = row0 + i;
        float* crow = &C[(size_t)grow * ldc + col0];
        if (MASK) {
#pragma unroll
            for (int j = 0; j < TN; j++) {
                float v = acc[i][j];
                if (col0 + j > grow) v = -INFINITY;
                acc[i][j] = v;
            }
        }
        float4 o0 = make_float4(acc[i][0], acc[i][1], acc[i][2], acc[i][3]);
        float4 o1 = make_float4(acc[i][4], acc[i][5], acc[i][6], acc[i][7]);
        *(float4*)&crow[0] = o0;
        *(float4*)&crow[4] = o1;
    }
}

// ---------------------------------------------------------------------------
// Row softmax (causal). Row i: valid entries [0, i]; zero-fill up to the
// 128-padded limit so the P@V kernel can read full BK tiles.
// ---------------------------------------------------------------------------
__global__ void softmax_kernel(float* __restrict__ S)
{
    const int row   = blockIdx.x;
    const int n     = row + 1;                    // valid length
    const int limit = ((row >> 7) + 1) << 7;      // padded to 128
    float* s = S + (size_t)row * N_CTX;

    __shared__ float red[32];
    const int lane = threadIdx.x & 31;
    const int wid  = threadIdx.x >> 5;

    // ---- max
    float m = -INFINITY;
    for (int j = threadIdx.x; j < n; j += 256) m = fmaxf(m, s[j]);
#pragma unroll
    for (int o = 16; o; o >>= 1) m = fmaxf(m, __shfl_xor_sync(0xffffffffu, m, o));
    if (lane == 0) red[wid] = m;
    __syncthreads();
    if (threadIdx.x < 32) {
        float v = (threadIdx.x < 8) ? red[threadIdx.x] : -INFINITY;
#pragma unroll
        for (int o = 4; o; o >>= 1) v = fmaxf(v, __shfl_xor_sync(0xffffffffu, v, o));
        if (threadIdx.x == 0) red[0] = v;
    }
    __syncthreads();
    m = red[0];
    __syncthreads();

    // ---- sum of exp
    float sum = 0.0f;
    for (int j = threadIdx.x; j < n; j += 256) sum += __expf(s[j] - m);
#pragma unroll
    for (int o = 16; o; o >>= 1) sum += __shfl_xor_sync(0xffffffffu, sum, o);
    if (lane == 0) red[wid] = sum;
    __syncthreads();
    if (threadIdx.x < 32) {
        float v = (threadIdx.x < 8) ? red[threadIdx.x] : 0.0f;
#pragma unroll
        for (int o = 4; o; o >>= 1) v += __shfl_xor_sync(0xffffffffu, v, o);
        if (threadIdx.x == 0) red[0] = v;
    }
    __syncthreads();
    const float inv = 1.0f / red[0];

    // ---- normalize + zero-pad to block limit
    for (int j = threadIdx.x; j < limit; j += 256) {
        float p = (j < n) ? __expf(s[j] - m) * inv : 0.0f;
        s[j] = p;
    }
}

// ---------------------------------------------------------------------------
extern "C" void kernel_launch(void* const* d_in, const int* in_sizes, int n_in,
                              void* d_out, int out_size)
{
    const float* E  = (const float*)d_in[0];   // [4096, 2048]
    const float* qk = (const float*)d_in[1];   // [2048, 2048]
    const float* ov = (const float*)d_in[2];   // [2048, 2048]
    float* out = (float*)d_out;                // [4096, 2048]

    float *Q, *V, *S;
    cudaGetSymbolAddress((void**)&Q, g_Q);
    cudaGetSymbolAddress((void**)&V, g_V);
    cudaGetSymbolAddress((void**)&S, g_S);

    dim3 blk(256);
    dim3 gNd(D_MODEL / BN, N_CTX / BM);   // 16 x 32
    dim3 gNN(N_CTX  / BN, N_CTX / BM);    // 32 x 32

    // Q = E @ qk
    gemm_kernel<false, false, false, false><<<gNd, blk>>>(
        E, qk, Q, N_CTX, D_MODEL, D_MODEL, D_MODEL, D_MODEL, D_MODEL);
    // V = E @ ov
    gemm_kernel<false, false, false, false><<<gNd, blk>>>(
        E, ov, V, N_CTX, D_MODEL, D_MODEL, D_MODEL, D_MODEL, D_MODEL);
    // S = Q @ E^T  (lower-triangle blocks only, causal mask on diagonal)
    gemm_kernel<true, true, false, true><<<gNN, blk>>>(
        Q, E, S, N_CTX, N_CTX, D_MODEL, D_MODEL, D_MODEL, N_CTX);
    // P = softmax_rows(S)   (in place, zero-padded to 128)
    softmax_kernel<<<N_CTX, blk>>>(S);
    // out = P @ V  (K limited to causal extent per row block)
    gemm_kernel<false, false, true, false><<<gNd, blk>>>(
        S, V, out, N_CTX, D_MODEL, N_CTX, N_CTX, D_MODEL, D_MODEL);
}

// round 8
// speedup vs baseline: 2.3940x; 2.3940x over previous
#include <cuda_runtime.h>
#include <cuda_fp16.h>
#include <math.h>
#include <stdint.h>

#define N_CTX   4096
#define D_MODEL 2048

// ---------------- scratch (allocation-free rule: device globals) ----------
__device__ float g_Q  [(size_t)N_CTX  * D_MODEL];   // E @ qk
__device__ float g_S  [(size_t)N_CTX  * N_CTX];     // scores -> probs
__device__ float g_Vt [(size_t)D_MODEL * N_CTX];    // (E @ ov)^T
__device__ float g_qkT[(size_t)D_MODEL * D_MODEL];
__device__ float g_ovT[(size_t)D_MODEL * D_MODEL];

// ---------------- helpers ---------------------------------------------------
__device__ __forceinline__ uint32_t smem_u32(const void* p) {
    uint32_t a;
    asm("{ .reg .u64 t; cvta.to.shared.u64 t, %1; cvt.u32.u64 %0, t; }"
        : "=r"(a) : "l"(p));
    return a;
}
#define SWZ(o) ((o) ^ (((o) >> 3) & 0x70))

__device__ __forceinline__ uint32_t f2h2(float x, float y) {
    __half2 h = __floats2half2_rn(x, y);
    return reinterpret_cast<uint32_t&>(h);
}
__device__ __forceinline__ void ldsm_x4(uint32_t* r, uint32_t addr) {
    asm volatile("ldmatrix.sync.aligned.m8n8.x4.shared.b16 {%0,%1,%2,%3}, [%4];"
                 : "=r"(r[0]), "=r"(r[1]), "=r"(r[2]), "=r"(r[3]) : "r"(addr));
}
__device__ __forceinline__ void mma16816(float* c, const uint32_t* a, const uint32_t* b) {
    asm volatile(
        "mma.sync.aligned.m16n8k16.row.col.f32.f16.f16.f32 "
        "{%0,%1,%2,%3}, {%4,%5,%6,%7}, {%8,%9}, {%0,%1,%2,%3};"
        : "+f"(c[0]), "+f"(c[1]), "+f"(c[2]), "+f"(c[3])
        : "r"(a[0]), "r"(a[1]), "r"(a[2]), "r"(a[3]), "r"(b[0]), "r"(b[1]));
}

// SMEM: four 128x64 f16 tiles, SW128 layout (128B rows), 16 KB each.
static constexpr int OFF_AH = 0;
static constexpr int OFF_AL = 16384;
static constexpr int OFF_BH = 32768;
static constexpr int OFF_BL = 49152;
static constexpr int SMEM_BYTES = 65536;

// ---------------------------------------------------------------------------
// Split-fp16 HMMA GEMM:  C[M,N] = A[M,K] @ B[N,K]^T   (fp32 in/out, f32 accum)
//   3 MMA terms per k-step: Ahi*Bhi + Ahi*Blo + Alo*Bhi  (lo*lo dropped)
//   SKIP_UPPER : skip CTA tiles with bx > by (causal block triangle)
//   KLIMIT     : Kend = min(K, (by+1)*128)  (causal P @ V)
//   MASK       : -inf where global col > global row (diagonal score blocks)
// ---------------------------------------------------------------------------
template<bool SKIP_UPPER, bool KLIMIT, bool MASK>
__global__ __launch_bounds__(256, 1)
void gemm_hmma(const float* __restrict__ A, const float* __restrict__ B,
               float* __restrict__ C, int K, int lda, int ldb, int ldc)
{
    extern __shared__ char sm[];
    const int bx = blockIdx.x, by = blockIdx.y;
    if (SKIP_UPPER && bx > by) return;

    int Kend = K;
    if (KLIMIT) { int lim = (by + 1) * 128; Kend = lim < K ? lim : K; }
    const int nc = Kend >> 6;     // 64-wide K chunks

    const uint32_t sb = smem_u32(sm);
    const int tid  = threadIdx.x;
    const int wid  = tid >> 5;
    const int lane = tid & 31;
    const int warpM = (wid & 1) * 64;   // 2 warps down M
    const int warpN = (wid >> 1) * 32;  // 4 warps across N

    float acc[4][4][4];
#pragma unroll
    for (int mt = 0; mt < 4; mt++)
#pragma unroll
        for (int nt = 0; nt < 4; nt++)
#pragma unroll
            for (int q = 0; q < 4; q++) acc[mt][nt][q] = 0.0f;

    const float* Ab = A + (size_t)by * 128 * lda;
    const float* Bb = B + (size_t)bx * 128 * ldb;

    // lane-dependent ldmatrix row/khalf components (constant across chunks)
    const int a_row_l  = lane & 15;
    const int a_kh_l   = ((lane >> 4) & 1) * 8;
    const int b_row_l  = (lane & 7) + ((lane >> 4) & 1) * 8;
    const int b_kh_l   = ((lane >> 3) & 1) * 8;

    for (int c = 0; c < nc; c++) {
        const int k0 = c << 6;
        __syncthreads();   // previous chunk fully consumed

        // ---- producer: load fp32, split to (hi, lo) f16, store swizzled ----
#pragma unroll
        for (int j = 0; j < 8; j++) {
            int i  = tid + (j << 8);        // 0..2047
            int r  = i >> 4;                // tile row 0..127
            int c4 = (i & 15) << 2;         // k offset (x4 floats)
            uint32_t so = SWZ((uint32_t)(r * 128 + (c4 << 1)));

            float4 va = *(const float4*)(Ab + (size_t)r * lda + k0 + c4);
            float axh = __half2float(__float2half_rn(va.x));
            float ayh = __half2float(__float2half_rn(va.y));
            float azh = __half2float(__float2half_rn(va.z));
            float awh = __half2float(__float2half_rn(va.w));
            *(uint2*)(sm + OFF_AH + so) = make_uint2(f2h2(va.x, va.y), f2h2(va.z, va.w));
            *(uint2*)(sm + OFF_AL + so) = make_uint2(f2h2(va.x - axh, va.y - ayh),
                                                     f2h2(va.z - azh, va.w - awh));

            float4 vb = *(const float4*)(Bb + (size_t)r * ldb + k0 + c4);
            float bxh = __half2float(__float2half_rn(vb.x));
            float byh = __half2float(__float2half_rn(vb.y));
            float bzh = __half2float(__float2half_rn(vb.z));
            float bwh = __half2float(__float2half_rn(vb.w));
            *(uint2*)(sm + OFF_BH + so) = make_uint2(f2h2(vb.x, vb.y), f2h2(vb.z, vb.w));
            *(uint2*)(sm + OFF_BL + so) = make_uint2(f2h2(vb.x - bxh, vb.y - byh),
                                                     f2h2(vb.z - bzh, vb.w - bwh));
        }
        __syncthreads();

        // ---- consumer: 4 k16 steps, 48 HMMA each --------------------------
#pragma unroll
        for (int kk = 0; kk < 4; kk++) {
            uint32_t aH[4][4], aL[4][4], bH[2][4], bL[2][4];
#pragma unroll
            for (int mt = 0; mt < 4; mt++) {
                int row = warpM + mt * 16 + a_row_l;
                uint32_t off = SWZ((uint32_t)(row * 128 + (kk * 16 + a_kh_l) * 2));
                ldsm_x4(aH[mt], sb + OFF_AH + off);
                ldsm_x4(aL[mt], sb + OFF_AL + off);
            }
#pragma unroll
            for (int np = 0; np < 2; np++) {
                int row = warpN + np * 16 + b_row_l;
                uint32_t off = SWZ((uint32_t)(row * 128 + (kk * 16 + b_kh_l) * 2));
                ldsm_x4(bH[np], sb + OFF_BH + off);
                ldsm_x4(bL[np], sb + OFF_BL + off);
            }
#pragma unroll
            for (int mt = 0; mt < 4; mt++)
#pragma unroll
                for (int nt = 0; nt < 4; nt++) {
                    float* cc = acc[mt][nt];
                    const uint32_t* bh = &bH[nt >> 1][(nt & 1) * 2];
                    const uint32_t* bl = &bL[nt >> 1][(nt & 1) * 2];
                    mma16816(cc, aH[mt], bh);
                    mma16816(cc, aH[mt], bl);
                    mma16816(cc, aL[mt], bh);
                }
        }
    }

    // ---- epilogue -----------------------------------------------------------
    const int g  = lane >> 2;
    const int t2 = (lane & 3) * 2;
#pragma unroll
    for (int mt = 0; mt < 4; mt++) {
        int grow0 = by * 128 + warpM + mt * 16 + g;
        int grow1 = grow0 + 8;
#pragma unroll
        for (int nt = 0; nt < 4; nt++) {
            int gcol = bx * 128 + warpN + nt * 8 + t2;
            float2 v0 = make_float2(acc[mt][nt][0], acc[mt][nt][1]);
            float2 v1 = make_float2(acc[mt][nt][2], acc[mt][nt][3]);
            if (MASK) {
                if (gcol     > grow0) v0.x = -INFINITY;
                if (gcol + 1 > grow0) v0.y = -INFINITY;
                if (gcol     > grow1) v1.x = -INFINITY;
                if (gcol + 1 > grow1) v1.y = -INFINITY;
            }
            *(float2*)(C + (size_t)grow0 * ldc + gcol) = v0;
            *(float2*)(C + (size_t)grow1 * ldc + gcol) = v1;
        }
    }
}

// ---------------------------------------------------------------------------
// 2048x2048 fp32 transpose (for qk, ov)
// ---------------------------------------------------------------------------
__global__ void transpose2048(const float* __restrict__ in, float* __restrict__ out)
{
    __shared__ float t[32][33];
    int x = blockIdx.x * 32 + threadIdx.x;
    int y = blockIdx.y * 32 + threadIdx.y;
#pragma unroll
    for (int j = 0; j < 32; j += 8)
        t[threadIdx.y + j][threadIdx.x] = in[(size_t)(y + j) * D_MODEL + x];
    __syncthreads();
    x = blockIdx.y * 32 + threadIdx.x;
    y = blockIdx.x * 32 + threadIdx.y;
#pragma unroll
    for (int j = 0; j < 32; j += 8)
        out[(size_t)(y + j) * D_MODEL + x] = t[threadIdx.x][threadIdx.y + j];
}

// ---------------------------------------------------------------------------
// Row softmax (causal), in place; zero-pads each row to its 128-block limit.
// ---------------------------------------------------------------------------
__global__ void softmax_kernel(float* __restrict__ S)
{
    const int row   = blockIdx.x;
    const int n     = row + 1;
    const int limit = ((row >> 7) + 1) << 7;
    float* s = S + (size_t)row * N_CTX;

    __shared__ float red[32];
    const int lane = threadIdx.x & 31;
    const int wid  = threadIdx.x >> 5;

    float m = -INFINITY;
    for (int j = threadIdx.x; j < n; j += 256) m = fmaxf(m, s[j]);
#pragma unroll
    for (int o = 16; o; o >>= 1) m = fmaxf(m, __shfl_xor_sync(0xffffffffu, m, o));
    if (lane == 0) red[wid] = m;
    __syncthreads();
    if (threadIdx.x < 32) {
        float v = (threadIdx.x < 8) ? red[threadIdx.x] : -INFINITY;
#pragma unroll
        for (int o = 4; o; o >>= 1) v = fmaxf(v, __shfl_xor_sync(0xffffffffu, v, o));
        if (threadIdx.x == 0) red[0] = v;
    }
    __syncthreads();
    m = red[0];
    __syncthreads();

    float sum = 0.0f;
    for (int j = threadIdx.x; j < n; j += 256) sum += __expf(s[j] - m);
#pragma unroll
    for (int o = 16; o; o >>= 1) sum += __shfl_xor_sync(0xffffffffu, sum, o);
    if (lane == 0) red[wid] = sum;
    __syncthreads();
    if (threadIdx.x < 32) {
        float v = (threadIdx.x < 8) ? red[threadIdx.x] : 0.0f;
#pragma unroll
        for (int o = 4; o; o >>= 1) v += __shfl_xor_sync(0xffffffffu, v, o);
        if (threadIdx.x == 0) red[0] = v;
    }
    __syncthreads();
    const float inv = 1.0f / red[0];

    for (int j = threadIdx.x; j < limit; j += 256) {
        float p = (j < n) ? __expf(s[j] - m) * inv : 0.0f;
        s[j] = p;
    }
}

// ---------------------------------------------------------------------------
extern "C" void kernel_launch(void* const* d_in, const int* in_sizes, int n_in,
                              void* d_out, int out_size)
{
    const float* E  = (const float*)d_in[0];   // [4096, 2048]
    const float* qk = (const float*)d_in[1];   // [2048, 2048]
    const float* ov = (const float*)d_in[2];   // [2048, 2048]
    float* out = (float*)d_out;                // [4096, 2048]

    float *Q, *S, *Vt, *qkT, *ovT;
    cudaGetSymbolAddress((void**)&Q,   g_Q);
    cudaGetSymbolAddress((void**)&S,   g_S);
    cudaGetSymbolAddress((void**)&Vt,  g_Vt);
    cudaGetSymbolAddress((void**)&qkT, g_qkT);
    cudaGetSymbolAddress((void**)&ovT, g_ovT);

    cudaFuncSetAttribute(gemm_hmma<false, false, false>,
                         cudaFuncAttributeMaxDynamicSharedMemorySize, SMEM_BYTES);
    cudaFuncSetAttribute(gemm_hmma<true, false, true>,
                         cudaFuncAttributeMaxDynamicSharedMemorySize, SMEM_BYTES);
    cudaFuncSetAttribute(gemm_hmma<false, true, false>,
                         cudaFuncAttributeMaxDynamicSharedMemorySize, SMEM_BYTES);

    dim3 tb(32, 8), tg(64, 64);
    transpose2048<<<tg, tb>>>(qk, qkT);
    transpose2048<<<tg, tb>>>(ov, ovT);

    // Q = E @ qk           (A=E [4096,2048], B=qkT [2048,2048])
    gemm_hmma<false, false, false><<<dim3(16, 32), 256, SMEM_BYTES>>>(
        E, qkT, Q, D_MODEL, D_MODEL, D_MODEL, D_MODEL);
    // Vt = (E @ ov)^T      (Vt[d][t] = sum_j ovT[d][j] * E[t][j])
    gemm_hmma<false, false, false><<<dim3(32, 16), 256, SMEM_BYTES>>>(
        ovT, E, Vt, D_MODEL, D_MODEL, D_MODEL, N_CTX);
    // S = Q @ E^T          (lower-triangle blocks; -inf mask on diagonal)
    gemm_hmma<true, false, true><<<dim3(32, 32), 256, SMEM_BYTES>>>(
        Q, E, S, D_MODEL, D_MODEL, D_MODEL, N_CTX);
    // P = softmax rows (in place, zero-padded to 128 blocks)
    softmax_kernel<<<N_CTX, 256>>>(S);
    // out = P @ Vt^T       (K limited to causal extent per row block)
    gemm_hmma<false, true, false><<<dim3(16, 32), 256, SMEM_BYTES>>>(
        S, Vt, out, N_CTX, N_CTX, N_CTX, D_MODEL);
}